// round 7
// baseline (speedup 1.0000x reference)
#include <cuda_runtime.h>

// Fixed problem shapes
#define T_STEPS 5
#define BS      32
#define C       64
#define H       64
#define W       64
#define VTH     1.0f
// gamma = DROP_RATE / BLOCK_SIZE^2 = 0.1 / 49
#define GAMMA   0.002040816326530612f

#define N_PLANES (T_STEPS * BS)               // 160
#define PLANE    (H * W)                      // 4096
#define PLANE4   (PLANE / 4)                  // 1024
#define ELEMS_PER_T (BS * C * H * W)          // 8388608
#define VEC_PER_T   (ELEMS_PER_T / 4)         // 2097152

#define MAX_SEEDS 1024                        // E[k] ~ 8.4/plane

// keep-mask as nibbles: d_nib[n*1024 + h*16 + wq] bit j == keep(h, 4*wq+j)
__device__ unsigned char d_nib[N_PLANES * PLANE4];   // 160 KB

// ---------------------------------------------------------------------------
// Kernel 1: sparse-seed block mask -> nibble bytes. One block per plane.
// Seeds (mr < gamma) ~8.4 per 64x64 plane: gather into smem list, then each
// thread emits 4 nibble-bytes: keep = !(exists seed with Cheb dist <= 3).
// ---------------------------------------------------------------------------
__global__ void __launch_bounds__(256) block_mask_kernel(const float4* __restrict__ mr4) {
    __shared__ int s_cnt;
    __shared__ int s_pts[MAX_SEEDS];   // packed (r << 8) | w

    const int n   = blockIdx.x;
    const int tid = threadIdx.x;
    if (tid == 0) s_cnt = 0;
    __syncthreads();

    #pragma unroll
    for (int j = 0; j < 4; ++j) {
        const int idx = tid + j * 256;                 // 0..1023 float4 index
        const float4 v = mr4[n * PLANE4 + idx];
        const int r  = idx >> 4;
        const int w0 = (idx & 15) << 2;
        if (v.x < GAMMA) { int s = atomicAdd(&s_cnt, 1); if (s < MAX_SEEDS) s_pts[s] = (r << 8) | (w0 + 0); }
        if (v.y < GAMMA) { int s = atomicAdd(&s_cnt, 1); if (s < MAX_SEEDS) s_pts[s] = (r << 8) | (w0 + 1); }
        if (v.z < GAMMA) { int s = atomicAdd(&s_cnt, 1); if (s < MAX_SEEDS) s_pts[s] = (r << 8) | (w0 + 2); }
        if (v.w < GAMMA) { int s = atomicAdd(&s_cnt, 1); if (s < MAX_SEEDS) s_pts[s] = (r << 8) | (w0 + 3); }
    }
    __syncthreads();

    const int k = (s_cnt < MAX_SEEDS) ? s_cnt : MAX_SEEDS;

    #pragma unroll
    for (int j = 0; j < 4; ++j) {
        const int idx = tid + j * 256;
        const int h   = idx >> 4;
        const int wb  = (idx & 15) << 2;
        unsigned nib = 0xFu;
        for (int i = 0; i < k; ++i) {
            const int p  = s_pts[i];
            const int pr = p >> 8;
            if (abs(pr - h) <= 3) {
                const int dw = (p & 255) - wb;
                if (dw >= -3 && dw <= 3) nib &= ~1u;
                if (dw >= -2 && dw <= 4) nib &= ~2u;
                if (dw >= -1 && dw <= 5) nib &= ~4u;
                if (dw >=  0 && dw <= 6) nib &= ~8u;
            }
        }
        d_nib[n * PLANE4 + idx] = (unsigned char)nib;
    }

    cudaTriggerProgrammaticLaunchCompletion();
}

// ---------------------------------------------------------------------------
// Kernel 2: LIF scan — R3's lean loop body (46.3us, 78% DRAM), with the float4
// bm load replaced by a 1-byte nibble load (coalesced 32B/warp, L2-hot).
// PDL-gated at top (mask kernel is ~1.5us).
// ---------------------------------------------------------------------------
__global__ void __launch_bounds__(256) lif_kernel(const float4* __restrict__ x,
                                                  float4* __restrict__ out) {
    cudaGridDependencySynchronize();

    const int v = blockIdx.x * 256 + threadIdx.x;   // grid exactly covers VEC_PER_T

    const int wq = v & 15;
    const int h  = (v >> 4) & 63;
    const int b  = v >> 16;
    const int nb_base = ((b << 6) + h) * 16 + wq;

    float4 u = make_float4(0.f, 0.f, 0.f, 0.f);

    #pragma unroll
    for (int t = 0; t < T_STEPS; ++t) {
        const float4 xt = x[t * VEC_PER_T + v];
        const unsigned nib = d_nib[(t * BS) * PLANE4 + nb_base];
        float4 o;

        u.x = (u.x > VTH) ? xt.x : fmaf(0.5f, u.x, xt.x);
        u.y = (u.y > VTH) ? xt.y : fmaf(0.5f, u.y, xt.y);
        u.z = (u.z > VTH) ? xt.z : fmaf(0.5f, u.z, xt.z);
        u.w = (u.w > VTH) ? xt.w : fmaf(0.5f, u.w, xt.w);

        o.x = (u.x > VTH && (nib & 1u)) ? 1.0f : 0.0f;
        o.y = (u.y > VTH && (nib & 2u)) ? 1.0f : 0.0f;
        o.z = (u.z > VTH && (nib & 4u)) ? 1.0f : 0.0f;
        o.w = (u.w > VTH && (nib & 8u)) ? 1.0f : 0.0f;

        out[t * VEC_PER_T + v] = o;
    }
}

extern "C" void kernel_launch(void* const* d_in, const int* in_sizes, int n_in,
                              void* d_out, int out_size) {
    const float4* x  = (const float4*)d_in[0];
    const float4* mr = (const float4*)d_in[1];
    float4* out      = (float4*)d_out;

    block_mask_kernel<<<N_PLANES, 256>>>(mr);

    // PDL launch: hides the (tiny) mask node's tail + launch ramp.
    cudaLaunchConfig_t cfg = {};
    cfg.gridDim  = dim3(VEC_PER_T / 256);
    cfg.blockDim = dim3(256);
    cfg.stream   = 0;
    cudaLaunchAttribute attr[1];
    attr[0].id = cudaLaunchAttributeProgrammaticStreamSerialization;
    attr[0].val.programmaticStreamSerializationAllowed = 1;
    cfg.attrs    = attr;
    cfg.numAttrs = 1;
    cudaLaunchKernelEx(&cfg, lif_kernel, x, out);
}

// round 8
// speedup vs baseline: 1.0221x; 1.0221x over previous
#include <cuda_runtime.h>

// Fixed problem shapes
#define T_STEPS 5
#define BS      32
#define C       64
#define H       64
#define W       64
#define VTH     1.0f
// gamma = DROP_RATE / BLOCK_SIZE^2 = 0.1 / 49
#define GAMMA   0.002040816326530612f

#define N_PLANES (T_STEPS * BS)               // 160
#define PLANE    (H * W)                      // 4096
#define PLANE4   (PLANE / 4)                  // 1024
#define ELEMS_PER_T (BS * C * H * W)          // 8388608
#define VEC_PER_T   (ELEMS_PER_T / 4)         // 2097152

#define MAX_SEEDS 1024                        // E[k] ~ 8.4/plane

// keep-mask as nibbles: d_nib[n*1024 + h*16 + wq] bit j == keep(h, 4*wq+j)
__device__ unsigned char d_nib[N_PLANES * PLANE4];   // 160 KB

// ---------------------------------------------------------------------------
// Kernel 1: sparse-seed block mask -> nibble bytes. One block per plane.
// ---------------------------------------------------------------------------
__global__ void __launch_bounds__(256) block_mask_kernel(const float4* __restrict__ mr4) {
    __shared__ int s_cnt;
    __shared__ int s_pts[MAX_SEEDS];   // packed (r << 8) | w

    const int n   = blockIdx.x;
    const int tid = threadIdx.x;
    if (tid == 0) s_cnt = 0;
    __syncthreads();

    #pragma unroll
    for (int j = 0; j < 4; ++j) {
        const int idx = tid + j * 256;                 // 0..1023 float4 index
        const float4 v = mr4[n * PLANE4 + idx];
        const int r  = idx >> 4;
        const int w0 = (idx & 15) << 2;
        if (v.x < GAMMA) { int s = atomicAdd(&s_cnt, 1); if (s < MAX_SEEDS) s_pts[s] = (r << 8) | (w0 + 0); }
        if (v.y < GAMMA) { int s = atomicAdd(&s_cnt, 1); if (s < MAX_SEEDS) s_pts[s] = (r << 8) | (w0 + 1); }
        if (v.z < GAMMA) { int s = atomicAdd(&s_cnt, 1); if (s < MAX_SEEDS) s_pts[s] = (r << 8) | (w0 + 2); }
        if (v.w < GAMMA) { int s = atomicAdd(&s_cnt, 1); if (s < MAX_SEEDS) s_pts[s] = (r << 8) | (w0 + 3); }
    }
    __syncthreads();

    const int k = (s_cnt < MAX_SEEDS) ? s_cnt : MAX_SEEDS;

    #pragma unroll
    for (int j = 0; j < 4; ++j) {
        const int idx = tid + j * 256;
        const int h   = idx >> 4;
        const int wb  = (idx & 15) << 2;
        unsigned nib = 0xFu;
        for (int i = 0; i < k; ++i) {
            const int p  = s_pts[i];
            const int pr = p >> 8;
            if (abs(pr - h) <= 3) {
                const int dw = (p & 255) - wb;
                if (dw >= -3 && dw <= 3) nib &= ~1u;
                if (dw >= -2 && dw <= 4) nib &= ~2u;
                if (dw >= -1 && dw <= 5) nib &= ~4u;
                if (dw >=  0 && dw <= 6) nib &= ~8u;
            }
        }
        d_nib[n * PLANE4 + idx] = (unsigned char)nib;
    }

    cudaTriggerProgrammaticLaunchCompletion();
}

// ---------------------------------------------------------------------------
// Kernel 2: LIF scan. x-prefetch BEFORE the PDL sync (overlaps mask kernel);
// nibble -> float4 via smem LUT (restores cheap FSEL select, ~90% broadcast).
// ---------------------------------------------------------------------------
__global__ void __launch_bounds__(256) lif_kernel(const float4* __restrict__ x,
                                                  float4* __restrict__ out) {
    __shared__ float4 s_lut[16];

    const int v = blockIdx.x * 256 + threadIdx.x;   // grid exactly covers VEC_PER_T

    // prefetch all 5 timesteps (independent of mask kernel)
    const float4 xt0 = x[v];
    const float4 xt1 = x[v + 1 * VEC_PER_T];
    const float4 xt2 = x[v + 2 * VEC_PER_T];
    const float4 xt3 = x[v + 3 * VEC_PER_T];
    const float4 xt4 = x[v + 4 * VEC_PER_T];

    if (threadIdx.x < 16) {
        const unsigned t = threadIdx.x;
        s_lut[t] = make_float4((t & 1u) ? 1.f : 0.f, (t & 2u) ? 1.f : 0.f,
                               (t & 4u) ? 1.f : 0.f, (t & 8u) ? 1.f : 0.f);
    }
    __syncthreads();

    cudaGridDependencySynchronize();

    const int wq = v & 15;
    const int h  = (v >> 4) & 63;
    const int b  = v >> 16;
    const int nb_base = ((b << 6) + h) * 16 + wq;

    float4 u = make_float4(0.f, 0.f, 0.f, 0.f);

    #define LIF_STEP(XT, T)                                                  \
    {                                                                        \
        const float4 bmt = s_lut[d_nib[(T * BS) * PLANE4 + nb_base]];        \
        float4 o;                                                            \
        u.x = (u.x > VTH) ? XT.x : fmaf(0.5f, u.x, XT.x);                    \
        u.y = (u.y > VTH) ? XT.y : fmaf(0.5f, u.y, XT.y);                    \
        u.z = (u.z > VTH) ? XT.z : fmaf(0.5f, u.z, XT.z);                    \
        u.w = (u.w > VTH) ? XT.w : fmaf(0.5f, u.w, XT.w);                    \
        o.x = (u.x > VTH) ? bmt.x : 0.0f;                                    \
        o.y = (u.y > VTH) ? bmt.y : 0.0f;                                    \
        o.z = (u.z > VTH) ? bmt.z : 0.0f;                                    \
        o.w = (u.w > VTH) ? bmt.w : 0.0f;                                    \
        out[v + T * VEC_PER_T] = o;                                          \
    }

    LIF_STEP(xt0, 0)
    LIF_STEP(xt1, 1)
    LIF_STEP(xt2, 2)
    LIF_STEP(xt3, 3)
    LIF_STEP(xt4, 4)
    #undef LIF_STEP
}

extern "C" void kernel_launch(void* const* d_in, const int* in_sizes, int n_in,
                              void* d_out, int out_size) {
    const float4* x  = (const float4*)d_in[0];
    const float4* mr = (const float4*)d_in[1];
    float4* out      = (float4*)d_out;

    block_mask_kernel<<<N_PLANES, 256>>>(mr);

    // PDL launch: lif's x-prefetch overlaps the mask kernel; the dependency
    // sync gates only the d_nib reads.
    cudaLaunchConfig_t cfg = {};
    cfg.gridDim  = dim3(VEC_PER_T / 256);
    cfg.blockDim = dim3(256);
    cfg.stream   = 0;
    cudaLaunchAttribute attr[1];
    attr[0].id = cudaLaunchAttributeProgrammaticStreamSerialization;
    attr[0].val.programmaticStreamSerializationAllowed = 1;
    cfg.attrs    = attr;
    cfg.numAttrs = 1;
    cudaLaunchKernelEx(&cfg, lif_kernel, x, out);
}